// round 14
// baseline (speedup 1.0000x reference)
#include <cuda_runtime.h>

// LFQ quantizer, factorized-softmax formulation, v9.
// v8 -> v9: SINGLE kernel. Finalize fused via fence/ticket/last-block;
// phase-B rank-1 accumulation uses packed fma.rn.f32x2 (FFMA2).
//
// probs_j = prod_d sigmoid(400*s_d(j)*x_d) = f(lo 8 bits) * g(hi 6 bits).

#define RG      37          // row groups
#define RPB     112         // rows per group (last group: 8 valid)
#define GRID_A  (RG * 4)    // 148 blocks = 1 per SM
#define NT_A    512
#define NCODES  16384
#define NROW    4096
#define NDIM    14

// scratch (__device__ globals; zero-init at load; reset by tail each call)
__device__ float g_avg[NCODES];                    // RED-accumulated sum of probs
__device__ float g_pH[RG];
__device__ float g_pC[RG];
__device__ unsigned int g_ticket;

// dynamic smem layout (floats)
#define OF_F    0                         // F  [RPB][256]
#define OF_SG   (RPB * 256)               // SG [RPB][64]
#define OF_SQ   (OF_SG + RPB * 64)        // SQ [RPB][NDIM][2]
#define OF_F03  (OF_SQ + RPB * NDIM * 2)  // F03 [RPB][16]
#define OF_F47  (OF_F03 + RPB * 16)       // F47 [RPB][16]
#define OF_WH   (OF_F47 + RPB * 16)       // SWH [16]
#define OF_WC   (OF_WH + 16)              // SWC [16]
#define SMEM_FLOATS (OF_WC + 16)
#define SMEM_BYTES  (SMEM_FLOATS * 4)     // ~166 KB -> 1 CTA/SM

__global__ __launch_bounds__(NT_A, 1) void lfq_fused_kernel(const float* __restrict__ x,
                                                            float* __restrict__ out)
{
    extern __shared__ __align__(16) float sm[];
    float* F   = sm + OF_F;
    float* SG  = sm + OF_SG;
    float* SQ  = sm + OF_SQ;
    float* F03 = sm + OF_F03;
    float* F47 = sm + OF_F47;
    float* SWH = sm + OF_WH;
    float* SWC = sm + OF_WC;

    const int t  = threadIdx.x;
    const int b  = blockIdx.x;
    const int rg = b >> 2;          // row group 0..36
    const int h  = b & 3;           // hi quarter
    const int row0  = rg * RPB;
    const int valid = min(RPB, NROW - row0);

    // ---- phase 0: per-element Bernoulli tables; h==0 also emits outputs/H/C ----
    float hS = 0.f, cS = 0.f;
#pragma unroll
    for (int k = 0; k < 4; k++) {
        const int e = t + NT_A * k;             // covers RPB*NDIM = 1568
        if (e < RPB * NDIM) {
            const int row = e / NDIM;
            const int d = e - row * NDIM;
            if (row < valid) {
                const float xv = x[(row0 + row) * NDIM + d];
                const int pos = xv > 0.f ? 1 : 0;
                const float au = fabsf(400.f * xv);
                const float ee = __expf(-au);                  // e^{-|u|}
                const float qmaj = __fdividef(1.f, 1.f + ee);  // sigmoid(|u|)
                const float qmin = ee * qmaj;                  // sigmoid(-|u|)
                SQ[(row * NDIM + d) * 2 + pos]     = qmaj;
                SQ[(row * NDIM + d) * 2 + 1 - pos] = qmin;
                if (h == 0) {
                    hS += log1pf(ee) + qmin * au;              // binary entropy (nats)
                    const float cm = fabsf(xv) - 1.f;
                    cS += cm * cm;
                    out[(row0 + row) * NDIM + d] = pos ? 1.f : -1.f;
                }
            } else {
                SQ[(row * NDIM + d) * 2 + 0] = 0.f;
                SQ[(row * NDIM + d) * 2 + 1] = 0.f;
            }
        }
    }
    if (h == 0) {
        if (t < valid) {
            int idx = 0;
#pragma unroll
            for (int d = 0; d < NDIM; d++)
                idx |= (x[(row0 + t) * NDIM + d] > 0.f) ? (1 << (13 - d)) : 0;
            out[NROW * NDIM + row0 + t] = (float)idx;
        }
#pragma unroll
        for (int off = 16; off > 0; off >>= 1) {
            hS += __shfl_down_sync(0xFFFFFFFFu, hS, off);
            cS += __shfl_down_sync(0xFFFFFFFFu, cS, off);
        }
        if ((t & 31) == 0) { SWH[t >> 5] = hS; SWC[t >> 5] = cS; }
    }
    __syncthreads();

    // ---- phase A1: f03 / f47 sub-products (2*RPB*16 = 3584 = 7*512) ----
#pragma unroll
    for (int k = 0; k < 7; k++) {
        const int e = t + NT_A * k;
        if (e < RPB * 16) {
            const int row = e >> 4, i = e & 15;
            const float* q = SQ + row * NDIM * 2;
            F03[e] = q[0 * 2 + (i & 1)] * q[1 * 2 + ((i >> 1) & 1)] *
                     q[2 * 2 + ((i >> 2) & 1)] * q[3 * 2 + ((i >> 3) & 1)];
        } else {
            const int e2 = e - RPB * 16;
            const int row = e2 >> 4, i = e2 & 15;
            const float* q = SQ + row * NDIM * 2;
            F47[e2] = q[4 * 2 + (i & 1)] * q[5 * 2 + ((i >> 1) & 1)] *
                      q[6 * 2 + ((i >> 2) & 1)] * q[7 * 2 + ((i >> 3) & 1)];
        }
    }
    __syncthreads();

    // ---- phase A2: full f table + g table (exact coverage) ----
#pragma unroll
    for (int k = 0; k < 56; k++) {
        const int e = t + NT_A * k;             // RPB*256 = 28672 = 56*512
        const int row = e >> 8, lo = e & 255;
        F[e] = F03[row * 16 + (lo & 15)] * F47[row * 16 + (lo >> 4)];
    }
#pragma unroll
    for (int k = 0; k < 14; k++) {
        const int e = t + NT_A * k;             // RPB*64 = 7168 = 14*512
        const int row = e >> 6, hc = e & 63;
        const float* q = SQ + row * NDIM * 2;
        SG[e] = q[8 * 2 + (hc & 1)] * q[9 * 2 + ((hc >> 1) & 1)] *
                q[10 * 2 + ((hc >> 2) & 1)] * q[11 * 2 + ((hc >> 3) & 1)] *
                q[12 * 2 + ((hc >> 4) & 1)] * q[13 * 2 + ((hc >> 5) & 1)];
    }
    __syncthreads();

    // ---- phase B: rank-1 accumulation with packed FFMA2 ----
    const int p   = t & 127;                    // lo pair: lo = 2p, 2p+1
    const int sub = t >> 7;                     // 0..3
    const int hi0 = h * 16 + sub * 4;           // this thread's 4 hi values

    unsigned long long acc0 = 0ull, acc1 = 0ull, acc2 = 0ull, acc3 = 0ull;

    for (int r = 0; r < valid; r++) {
        const unsigned long long f2 =
            *reinterpret_cast<const unsigned long long*>(F + r * 256 + 2 * p);   // LDS.64
        const float4 gv = *reinterpret_cast<const float4*>(SG + r * 64 + hi0);   // LDS.128 bcast
        unsigned long long g2;
        unsigned int gu;
        gu = __float_as_uint(gv.x);
        asm("mov.b64 %0, {%1, %1};" : "=l"(g2) : "r"(gu));
        asm("fma.rn.f32x2 %0, %1, %2, %0;" : "+l"(acc0) : "l"(f2), "l"(g2));
        gu = __float_as_uint(gv.y);
        asm("mov.b64 %0, {%1, %1};" : "=l"(g2) : "r"(gu));
        asm("fma.rn.f32x2 %0, %1, %2, %0;" : "+l"(acc1) : "l"(f2), "l"(g2));
        gu = __float_as_uint(gv.z);
        asm("mov.b64 %0, {%1, %1};" : "=l"(g2) : "r"(gu));
        asm("fma.rn.f32x2 %0, %1, %2, %0;" : "+l"(acc2) : "l"(f2), "l"(g2));
        gu = __float_as_uint(gv.w);
        asm("mov.b64 %0, {%1, %1};" : "=l"(g2) : "r"(gu));
        asm("fma.rn.f32x2 %0, %1, %2, %0;" : "+l"(acc3) : "l"(f2), "l"(g2));
    }

    // RED-accumulate into the 64 KB avg_probs vector (low half = F[2p] = code lo 2p)
    {
        const int j0 = hi0 * 256 + 2 * p;
        atomicAdd(&g_avg[j0],           __uint_as_float((unsigned)(acc0)));
        atomicAdd(&g_avg[j0 + 1],       __uint_as_float((unsigned)(acc0 >> 32)));
        atomicAdd(&g_avg[j0 + 256],     __uint_as_float((unsigned)(acc1)));
        atomicAdd(&g_avg[j0 + 257],     __uint_as_float((unsigned)(acc1 >> 32)));
        atomicAdd(&g_avg[j0 + 512],     __uint_as_float((unsigned)(acc2)));
        atomicAdd(&g_avg[j0 + 513],     __uint_as_float((unsigned)(acc2 >> 32)));
        atomicAdd(&g_avg[j0 + 768],     __uint_as_float((unsigned)(acc3)));
        atomicAdd(&g_avg[j0 + 769],     __uint_as_float((unsigned)(acc3 >> 32)));
    }

    if (h == 0 && t == 0) {
        float H = 0.f, C = 0.f;
#pragma unroll
        for (int w = 0; w < 16; w++) { H += SWH[w]; C += SWC[w]; }
        g_pH[rg] = H; g_pC[rg] = C;
    }

    // ---- ticket: release all this block's writes, last block finalizes ----
    __threadfence();                 // every thread fences its own REDs/stores
    __syncthreads();
    __shared__ int sh_last;
    if (t == 0)
        sh_last = (atomicAdd(&g_ticket, 1u) == GRID_A - 1) ? 1 : 0;
    __syncthreads();
    if (!sh_last) return;
    __threadfence();                 // acquire side

    // ---- tail (single block): codebook entropy + scalars + state reset ----
    float* red = sm;                 // reuse smem
    float term = 0.f;
#pragma unroll
    for (int k = 0; k < 32; k++) {
        const int j = k * NT_A + t;
        const float a = g_avg[j] * (1.f / (float)NROW);
        term += a * __logf(a + 1e-5f);          // a==0 -> 0, matches ref
        g_avg[j] = 0.f;                          // reset for next replay
    }
    red[t] = term;
    __syncthreads();
#pragma unroll
    for (int off = 256; off > 0; off >>= 1) {
        if (t < off) red[t] += red[t + off];
        __syncthreads();
    }
    const float sumT = red[0];
    __syncthreads();

    float* fred = sm + NT_A;
    if (t < 64) fred[t] = (t < RG) ? g_pH[t] : 0.f;
    __syncthreads();
#pragma unroll
    for (int off = 32; off > 0; off >>= 1) {
        if (t < off) fred[t] += fred[t + off];
        __syncthreads();
    }
    const float sumH = fred[0];
    __syncthreads();
    if (t < 64) fred[t] = (t < RG) ? g_pC[t] : 0.f;
    __syncthreads();
#pragma unroll
    for (int off = 32; off > 0; off >>= 1) {
        if (t < off) fred[t] += fred[t + off];
        __syncthreads();
    }
    const float sumC = fred[0];

    if (t == 0) {
        const float per_sample = sumH * (1.f / (float)NROW);
        const float cb_entropy = -sumT;
        float* sc = out + NROW * NDIM + NROW;
        sc[0] = per_sample;
        sc[1] = cb_entropy;
        sc[2] = per_sample - cb_entropy;
        sc[3] = sumC * (1.f / (float)(NROW * NDIM));
        g_ticket = 0u;                           // reset for next replay
    }
}

extern "C" void kernel_launch(void* const* d_in, const int* in_sizes, int n_in,
                              void* d_out, int out_size)
{
    (void)in_sizes; (void)n_in; (void)out_size;
    const float* x = (const float*)d_in[0];   // [2,2048,14] float32
    float* out = (float*)d_out;

    cudaFuncSetAttribute(lfq_fused_kernel,
                         cudaFuncAttributeMaxDynamicSharedMemorySize, SMEM_BYTES);
    lfq_fused_kernel<<<GRID_A, NT_A, SMEM_BYTES>>>(x, out);
}